// round 13
// baseline (speedup 1.0000x reference)
#include <cuda_runtime.h>

#define NTN 500000
#define NCN 100000
#define NMN 20000
#define NE  500000
#define FIN 128
#define FHID 64

#define NCHC 25          // ceil(NCN/4096)
#define NCHM 5           // ceil(NMN/4096)
#define NBC 1563         // ceil(NCN/64)
#define NBM 313          // ceil(NMN/64)
#define SASTR 132        // smem A stride (floats): 528 B rows, 16B-aligned
#define AGG_SMEM (64 * SASTR * 4 + FIN * FHID * 4)   // sA + staged W0 = 66560 B

// ---------------- device scratch ----------------
__device__ float g_p_c[NCN * 2];
__device__ float g_p_m[NMN * 2];
__device__ int   g_cnt_t2c[NCN];
__device__ int   g_cnt_t2m[NMN];
__device__ int   g_cnt_c2t[NTN];
__device__ int   g_cnt_m2t[NTN];
__device__ int   g_off_c[NCN];
__device__ int   g_off_m[NMN];
__device__ int   g_cur_c[NCN];
__device__ int   g_cur_m[NMN];
__device__ int   g_eid_c[NE];
__device__ int   g_eid_m[NE];
__device__ int   g_csum[NCHC + NCHM];
__device__ float g_M_c[FHID * 2];
__device__ float g_M_m[FHID * 2];
__device__ float g_b2_c[2];
__device__ float g_b2_m[2];

// ---------------- kernels ----------------

__global__ void initA_kernel() {            // CSR-side counters
    int i = blockIdx.x * blockDim.x + threadIdx.x;
    int stride = gridDim.x * blockDim.x;
    for (int j = i; j < NCN; j += stride) g_cnt_t2c[j] = 0;
    for (int j = i; j < NMN; j += stride) g_cnt_t2m[j] = 0;
}

__global__ void initB_kernel() {            // scatter-side counters
    int i = blockIdx.x * blockDim.x + threadIdx.x;
    int stride = gridDim.x * blockDim.x;
    for (int j = i; j < NTN; j += stride) { g_cnt_c2t[j] = 0; g_cnt_m2t[j] = 0; }
}

// 2 edges/thread (int2 loads, MLP=2). First NE/2 threads: t2c, next NE/2: t2m.
__global__ void countA_kernel(const int* __restrict__ d_t2c, const int* __restrict__ d_t2m) {
    int i = blockIdx.x * blockDim.x + threadIdx.x;
    if (i >= NE) return;
    if (i < NE / 2) {
        int2 d = ((const int2*)d_t2c)[i];
        atomicAdd(&g_cnt_t2c[d.x], 1);
        atomicAdd(&g_cnt_t2c[d.y], 1);
    } else {
        int2 d = ((const int2*)d_t2m)[i - NE / 2];
        atomicAdd(&g_cnt_t2m[d.x], 1);
        atomicAdd(&g_cnt_t2m[d.y], 1);
    }
}

__global__ void countB_kernel(const int* __restrict__ d_c2t, const int* __restrict__ d_m2t) {
    int i = blockIdx.x * blockDim.x + threadIdx.x;
    if (i >= NE) return;
    if (i < NE / 2) {
        int2 d = ((const int2*)d_c2t)[i];
        atomicAdd(&g_cnt_c2t[d.x], 1);
        atomicAdd(&g_cnt_c2t[d.y], 1);
    } else {
        int2 d = ((const int2*)d_m2t)[i - NE / 2];
        atomicAdd(&g_cnt_m2t[d.x], 1);
        atomicAdd(&g_cnt_m2t[d.y], 1);
    }
}

// Phase 1: per-4096-chunk exclusive scan + chunk total. block=1024, int4/thread.
__global__ void scan_local_kernel() {
    int cb = blockIdx.x;
    const int* cnt; int* off; int n, chunk;
    if (cb < NCHC) { cnt = g_cnt_t2c; off = g_off_c; n = NCN; chunk = cb; }
    else           { cnt = g_cnt_t2m; off = g_off_m; n = NMN; chunk = cb - NCHC; }

    __shared__ int wsum[32];
    int t = threadIdx.x;
    int i = chunk * 4096 + t * 4;
    int4 v = make_int4(0, 0, 0, 0);
    if (i < n) v = ((const int4*)cnt)[i >> 2];
    int s0 = v.x, s1 = s0 + v.y, s2 = s1 + v.z, s3 = s2 + v.w;
    int x = s3;
    #pragma unroll
    for (int o = 1; o < 32; o <<= 1) {
        int y = __shfl_up_sync(0xffffffffu, x, o);
        if ((t & 31) >= o) x += y;
    }
    if ((t & 31) == 31) wsum[t >> 5] = x;
    __syncthreads();
    if (t < 32) {
        int w = wsum[t], xs = w;
        #pragma unroll
        for (int o = 1; o < 32; o <<= 1) {
            int y = __shfl_up_sync(0xffffffffu, xs, o);
            if (t >= o) xs += y;
        }
        if (t == 31) g_csum[cb] = xs;
        wsum[t] = xs - w;
    }
    __syncthreads();
    int excl = wsum[t >> 5] + (x - s3);
    if (i < n) {
        int4 o4 = make_int4(excl, excl + s0, excl + s1, excl + s2);
        ((int4*)off)[i >> 2] = o4;
    }
}

// Phase 2+3 fused: each block sums preceding chunk totals itself (<=25 ints),
// adds base, and initializes cur = off (fill cursor).
__global__ void scan_addbase_kernel() {
    int cb = blockIdx.x;
    __shared__ int sbase;
    if (threadIdx.x == 0) {
        int lo = (cb < NCHC) ? 0 : NCHC;
        int a = 0;
        for (int i = lo; i < cb; i++) a += g_csum[i];
        sbase = a;
    }
    __syncthreads();
    int bval = sbase;
    int* off; int* cur; int n, chunk;
    if (cb < NCHC) { off = g_off_c; cur = g_cur_c; n = NCN; chunk = cb; }
    else           { off = g_off_m; cur = g_cur_m; n = NMN; chunk = cb - NCHC; }
    int i = chunk * 4096 + threadIdx.x * 4;
    if (i < n) {
        int4 o = ((int4*)off)[i >> 2];
        o.x += bval; o.y += bval; o.z += bval; o.w += bval;
        ((int4*)off)[i >> 2] = o;
        ((int4*)cur)[i >> 2] = o;
    }
}

// Fill both CSRs; 2 edges/thread (int2 loads, MLP=2). cur starts at off.
__global__ void fill_all_kernel(const int* __restrict__ src_c, const int* __restrict__ dst_c,
                                const int* __restrict__ src_m, const int* __restrict__ dst_m) {
    int i = blockIdx.x * blockDim.x + threadIdx.x;
    if (i >= NE) return;
    if (i < NE / 2) {
        int2 d = ((const int2*)dst_c)[i];
        int2 s = ((const int2*)src_c)[i];
        int p0 = atomicAdd(&g_cur_c[d.x], 1);
        int p1 = atomicAdd(&g_cur_c[d.y], 1);
        g_eid_c[p0] = s.x;
        g_eid_c[p1] = s.y;
    } else {
        int j = i - NE / 2;
        int2 d = ((const int2*)dst_m)[j];
        int2 s = ((const int2*)src_m)[j];
        int p0 = atomicAdd(&g_cur_m[d.x], 1);
        int p1 = atomicAdd(&g_cur_m[d.y], 1);
        g_eid_m[p0] = s.x;
        g_eid_m[p1] = s.y;
    }
}

// Tiny: M = W1 @ Wf (64x2), b2 = b1 @ Wf for both relations. One block, off critical path.
__global__ void make_M_kernel(const float* __restrict__ W1c, const float* __restrict__ b1c,
                              const float* __restrict__ W1m, const float* __restrict__ b1m,
                              const float* __restrict__ Wf) {
    __shared__ float sWf[FHID * 2];
    int t = threadIdx.x;  // 256 threads
    if (t < FHID * 2) sWf[t] = Wf[t];
    __syncthreads();
    const float* W1 = (t < 128) ? W1c : W1m;
    float* Mo = (t < 128) ? g_M_c : g_M_m;
    int tt = t & 127;
    int k = tt >> 1, o = tt & 1;
    float s = 0.f;
    #pragma unroll 8
    for (int j = 0; j < FHID; j++) s += W1[k * FHID + j] * sWf[j * 2 + o];
    Mo[k * 2 + o] = s;
    if (t < 2) {
        float s2 = 0.f;
        #pragma unroll 8
        for (int j = 0; j < FHID; j++) s2 += b1c[j] * sWf[j * 2 + t];
        g_b2_c[t] = s2;
    } else if (t < 4) {
        int oo = t - 2;
        float s2 = 0.f;
        #pragma unroll 8
        for (int j = 0; j < FHID; j++) s2 += b1m[j] * sWf[j * 2 + oo];
        g_b2_m[oo] = s2;
    }
}

// Fused gather-aggregate + layer0 GEMM + projection. 64 nodes/block, 256 threads.
// W0 staged in smem. Merchant blocks FIRST (avg degree 25 vs 5).
// Dynamic smem layout: sA[64*SASTR] | sWlo[FIN*8 float4] | sWhi[FIN*8 float4]
__global__ void __launch_bounds__(256) aggmm_kernel(
        const float* __restrict__ feat,
        const float* __restrict__ W0c, const float* __restrict__ b0c,
        const float* __restrict__ W0m, const float* __restrict__ b0m) {
    extern __shared__ float dsm[];
    float* sA = dsm;
    float4* sWlo = (float4*)(dsm + 64 * SASTR);
    float4* sWhi = sWlo + FIN * 8;

    bool isC = blockIdx.x >= NBM;
    int base = (isC ? blockIdx.x - NBM : blockIdx.x) * 64;
    int n = isC ? NCN : NMN;
    const int*   off = isC ? g_off_c : g_off_m;
    const int*   cnt = isC ? g_cnt_t2c : g_cnt_t2m;
    const int*   eid = isC ? g_eid_c : g_eid_m;
    const float* W0  = isC ? W0c : W0m;
    const float* b0  = isC ? b0c : b0m;
    const float* M   = isC ? g_M_c : g_M_m;
    const float* b2  = isC ? g_b2_c : g_b2_m;
    float*       pout = isC ? g_p_c : g_p_m;

    int t = threadIdx.x;
    int w = t >> 5, lane = t & 31;
    const float4* f4 = (const float4*)feat;

    // ---- Stage W0 into smem (contiguous 128B per k-row -> conflict-free LDS.128) ----
    {
        const float4* W4 = (const float4*)W0;
        #pragma unroll
        for (int i = t; i < FIN * 8; i += 256) {
            sWlo[i] = __ldg(W4 + 2 * i);
            sWhi[i] = __ldg(W4 + 2 * i + 1);
        }
    }

    // ---- Phase 1: gather-aggregate into smem (MLP=8) ----
    #pragma unroll 1
    for (int i = 0; i < 8; i++) {
        int nd = w * 8 + i;
        int gn = base + nd;
        float4 acc = make_float4(0.f, 0.f, 0.f, 0.f);
        if (gn < n) {
            int o = off[gn], c = cnt[gn];
            for (int b = 0; b < c; b += 32) {
                int m = min(32, c - b);
                int sreg = (lane < m) ? eid[o + b + lane] : 0;
                for (int j0 = 0; j0 < m; j0 += 8) {
                    int jm = min(8, m - j0);
                    float4 v[8];
                    #pragma unroll
                    for (int j = 0; j < 8; j++) {
                        int s = __shfl_sync(0xffffffffu, sreg, j0 + j);
                        if (j < jm) v[j] = __ldg(f4 + (size_t)s * (FIN / 4) + lane);
                    }
                    #pragma unroll
                    for (int j = 0; j < 8; j++) {
                        if (j < jm) {
                            acc.x += v[j].x; acc.y += v[j].y; acc.z += v[j].z; acc.w += v[j].w;
                        }
                    }
                }
            }
        }
        ((float4*)(sA + nd * SASTR))[lane] = acc;
    }
    __syncthreads();   // covers sA and staged W0

    // ---- Phase 2: GEMM (W from smem) + epilogue ----
    int cg = t & 7;       // col group: cols [cg*8, cg*8+8)
    int ng = t >> 3;      // 0..31; this thread owns nodes ng and ng+32

    unsigned long long acc[2][4];
    #pragma unroll
    for (int a = 0; a < 2; a++)
        #pragma unroll
        for (int p = 0; p < 4; p++) acc[a][p] = 0ull;

    const ulonglong2* Wlo8 = (const ulonglong2*)sWlo;
    const ulonglong2* Whi8 = (const ulonglong2*)sWhi;
    #pragma unroll 2
    for (int k = 0; k < FIN; k++) {
        float a0 = sA[ng * SASTR + k];
        float a1 = sA[(ng + 32) * SASTR + k];
        unsigned long long aa0, aa1;
        asm("mov.b64 %0,{%1,%1};" : "=l"(aa0) : "f"(a0));
        asm("mov.b64 %0,{%1,%1};" : "=l"(aa1) : "f"(a1));
        ulonglong2 wlo = Wlo8[k * 8 + cg];
        ulonglong2 whi = Whi8[k * 8 + cg];
        #define FMA2(A, B, Cc) asm("fma.rn.f32x2 %0,%1,%2,%0;" : "+l"(A) : "l"(B), "l"(Cc))
        FMA2(acc[0][0], aa0, wlo.x); FMA2(acc[0][1], aa0, wlo.y);
        FMA2(acc[0][2], aa0, whi.x); FMA2(acc[0][3], aa0, whi.y);
        FMA2(acc[1][0], aa1, wlo.x); FMA2(acc[1][1], aa1, wlo.y);
        FMA2(acc[1][2], aa1, whi.x); FMA2(acc[1][3], aa1, whi.y);
        #undef FMA2
    }

    #pragma unroll
    for (int a = 0; a < 2; a++) {
        int gn = base + ng + a * 32;
        int c = (gn < n) ? cnt[gn] : 0;
        float p0 = 0.f, p1 = 0.f;
        if (c > 0) {
            float inv = 1.f / (float)c;
            #pragma unroll
            for (int p = 0; p < 4; p++) {
                float zlo, zhi;
                asm("mov.b64 {%0,%1},%2;" : "=f"(zlo), "=f"(zhi) : "l"(acc[a][p]));
                int col = cg * 8 + 2 * p;
                float h = zlo * inv + b0[col];
                h = (h > 0.f) ? h : 0.01f * h;
                p0 += h * M[col * 2];
                p1 += h * M[col * 2 + 1];
                h = zhi * inv + b0[col + 1];
                h = (h > 0.f) ? h : 0.01f * h;
                p0 += h * M[(col + 1) * 2];
                p1 += h * M[(col + 1) * 2 + 1];
            }
        }
        #pragma unroll
        for (int o = 4; o; o >>= 1) {
            p0 += __shfl_down_sync(0xffffffffu, p0, o, 8);
            p1 += __shfl_down_sync(0xffffffffu, p1, o, 8);
        }
        if (cg == 0 && gn < n) {
            pout[gn * 2]     = p0 + b2[0];
            pout[gn * 2 + 1] = p1 + b2[1];
        }
    }
}

__global__ void out_init_kernel(float* __restrict__ out, const float* __restrict__ bf) {
    int i = blockIdx.x * blockDim.x + threadIdx.x;
    if (i < NTN) ((float2*)out)[i] = make_float2(bf[0], bf[1]);
}

// Final scatter: 4 edges/thread (int4 loads, MLP=4). First NE/4 threads: c2t, rest: m2t.
__global__ void scatter_all_kernel(const int* __restrict__ src_c, const int* __restrict__ dst_c,
                                   const int* __restrict__ src_m, const int* __restrict__ dst_m,
                                   float* __restrict__ out) {
    int i = blockIdx.x * blockDim.x + threadIdx.x;
    if (i >= NE / 2) return;
    const int* srcp; const int* dstp; const float* p; const int* cnt; int j;
    if (i < NE / 4) { srcp = src_c; dstp = dst_c; p = g_p_c; cnt = g_cnt_c2t; j = i; }
    else            { srcp = src_m; dstp = dst_m; p = g_p_m; cnt = g_cnt_m2t; j = i - NE / 4; }
    int4 s4 = ((const int4*)srcp)[j];
    int4 d4 = ((const int4*)dstp)[j];
    int ss[4] = {s4.x, s4.y, s4.z, s4.w};
    int dd[4] = {d4.x, d4.y, d4.z, d4.w};
    float2 pv[4];
    int cv[4];
    #pragma unroll
    for (int e = 0; e < 4; e++) {
        pv[e] = __ldg((const float2*)p + ss[e]);
        cv[e] = __ldg(&cnt[dd[e]]);
    }
    #pragma unroll
    for (int e = 0; e < 4; e++) {
        float inv = 1.f / (float)cv[e];
        float a = pv[e].x * inv;
        float b = pv[e].y * inv;
        float* ap = out + 2 * (size_t)dd[e];
        asm volatile("red.global.add.v2.f32 [%0], {%1,%2};"
                     :: "l"(ap), "f"(a), "f"(b) : "memory");
    }
}

// ---------------- launch ----------------
extern "C" void kernel_launch(void* const* d_in, const int* in_sizes, int n_in,
                              void* d_out, int out_size) {
    const float* feat    = (const float*)d_in[0];
    const int* src_c2t   = (const int*)d_in[3];
    const int* dst_c2t   = (const int*)d_in[4];
    const int* src_m2t   = (const int*)d_in[5];
    const int* dst_m2t   = (const int*)d_in[6];
    const int* src_t2c   = (const int*)d_in[7];
    const int* dst_t2c   = (const int*)d_in[8];
    const int* src_t2m   = (const int*)d_in[9];
    const int* dst_t2m   = (const int*)d_in[10];
    const float* W1_c2t  = (const float*)d_in[13];
    const float* b1_c2t  = (const float*)d_in[14];
    const float* W1_m2t  = (const float*)d_in[17];
    const float* b1_m2t  = (const float*)d_in[18];
    const float* W0_t2c  = (const float*)d_in[19];
    const float* b0_t2c  = (const float*)d_in[20];
    const float* W0_t2m  = (const float*)d_in[23];
    const float* b0_t2m  = (const float*)d_in[24];
    const float* Wf      = (const float*)d_in[27];
    const float* bf      = (const float*)d_in[28];
    float* out = (float*)d_out;

    const int TB = 256;

    // Allow >48KB dynamic smem for aggmm (host-side attribute; not a capture op).
    cudaFuncSetAttribute(aggmm_kernel, cudaFuncAttributeMaxDynamicSharedMemorySize, AGG_SMEM);

    // One side stream (proven-clean resource pattern).
    cudaStream_t s2;
    cudaStreamCreateWithFlags(&s2, cudaStreamNonBlocking);
    cudaEvent_t evF, evB;
    cudaEventCreateWithFlags(&evF, cudaEventDisableTiming);
    cudaEventCreateWithFlags(&evB, cudaEventDisableTiming);

    cudaEventRecord(evF, 0);
    cudaStreamWaitEvent(s2, evF, 0);

    // stream B: scatter-side counts + output init + fused-weight precompute.
    initB_kernel<<<1024, TB, 0, s2>>>();
    countB_kernel<<<(NE + TB - 1) / TB, TB, 0, s2>>>(dst_c2t, dst_m2t);
    out_init_kernel<<<(NTN + TB - 1) / TB, TB, 0, s2>>>(out, bf);
    make_M_kernel<<<1, 256, 0, s2>>>(W1_c2t, b1_c2t, W1_m2t, b1_m2t, Wf);
    cudaEventRecord(evB, s2);

    // stream A (default): CSR build -> fused agg+GEMM -> scatter
    initA_kernel<<<512, TB>>>();
    countA_kernel<<<(NE + TB - 1) / TB, TB>>>(dst_t2c, dst_t2m);
    scan_local_kernel<<<NCHC + NCHM, 1024>>>();
    scan_addbase_kernel<<<NCHC + NCHM, 1024>>>();
    fill_all_kernel<<<(NE + TB - 1) / TB, TB>>>(src_t2c, dst_t2c, src_t2m, dst_t2m);

    cudaStreamWaitEvent((cudaStream_t)0, evB, 0);   // make_M before aggmm; counts/out_init before scatter
    aggmm_kernel<<<NBC + NBM, 256, AGG_SMEM>>>(feat, W0_t2c, b0_t2c, W0_t2m, b0_t2m);
    scatter_all_kernel<<<(NE / 2 + TB - 1) / TB, TB>>>(src_c2t, dst_c2t, src_m2t, dst_m2t, out);
}

// round 14
// speedup vs baseline: 1.0469x; 1.0469x over previous
#include <cuda_runtime.h>

#define NTN 500000
#define NCN 100000
#define NMN 20000
#define NE  500000
#define FIN 128
#define FHID 64

#define NCHC 25          // ceil(NCN/4096)
#define NCHM 5           // ceil(NMN/4096)
#define NBC 1563         // ceil(NCN/64)
#define NBM 313          // ceil(NMN/64)
#define SASTR 132        // smem A stride (floats): 528 B rows, 16B-aligned
#define AGG_SMEM (64 * SASTR * 4 + FIN * FHID * 4)   // sA + staged W0 = 66560 B

// ---------------- device scratch ----------------
__device__ float g_p_c[NCN * 2];
__device__ float g_p_m[NMN * 2];
__device__ int   g_cnt_t2c[NCN];
__device__ int   g_cnt_t2m[NMN];
__device__ int   g_cnt_c2t[NTN];
__device__ int   g_cnt_m2t[NTN];
__device__ int   g_off_c[NCN];
__device__ int   g_off_m[NMN];
__device__ int   g_cur_c[NCN];
__device__ int   g_cur_m[NMN];
__device__ int   g_eid_c[NE];
__device__ int   g_eid_m[NE];
__device__ int   g_csum[NCHC + NCHM];
__device__ float g_M_c[FHID * 2];
__device__ float g_M_m[FHID * 2];
__device__ float g_b2_c[2];
__device__ float g_b2_m[2];

// ---------------- kernels ----------------

__global__ void initA_kernel() {            // CSR-side counters
    int i = blockIdx.x * blockDim.x + threadIdx.x;
    int stride = gridDim.x * blockDim.x;
    for (int j = i; j < NCN; j += stride) g_cnt_t2c[j] = 0;
    for (int j = i; j < NMN; j += stride) g_cnt_t2m[j] = 0;
}

__global__ void initB_kernel() {            // scatter-side counters
    int i = blockIdx.x * blockDim.x + threadIdx.x;
    int stride = gridDim.x * blockDim.x;
    for (int j = i; j < NTN; j += stride) { g_cnt_c2t[j] = 0; g_cnt_m2t[j] = 0; }
}

__global__ void countA_kernel(const int* __restrict__ d_t2c, const int* __restrict__ d_t2m) {
    int i = blockIdx.x * blockDim.x + threadIdx.x;
    if (i >= 2 * NE) return;
    if (i < NE) atomicAdd(&g_cnt_t2c[d_t2c[i]], 1);
    else        atomicAdd(&g_cnt_t2m[d_t2m[i - NE]], 1);
}

__global__ void countB_kernel(const int* __restrict__ d_c2t, const int* __restrict__ d_m2t) {
    int i = blockIdx.x * blockDim.x + threadIdx.x;
    if (i >= 2 * NE) return;
    if (i < NE) atomicAdd(&g_cnt_c2t[d_c2t[i]], 1);
    else        atomicAdd(&g_cnt_m2t[d_m2t[i - NE]], 1);
}

// Phase 1: per-4096-chunk exclusive scan + chunk total. block=1024, int4/thread.
__global__ void scan_local_kernel() {
    int cb = blockIdx.x;
    const int* cnt; int* off; int n, chunk;
    if (cb < NCHC) { cnt = g_cnt_t2c; off = g_off_c; n = NCN; chunk = cb; }
    else           { cnt = g_cnt_t2m; off = g_off_m; n = NMN; chunk = cb - NCHC; }

    __shared__ int wsum[32];
    int t = threadIdx.x;
    int i = chunk * 4096 + t * 4;
    int4 v = make_int4(0, 0, 0, 0);
    if (i < n) v = ((const int4*)cnt)[i >> 2];
    int s0 = v.x, s1 = s0 + v.y, s2 = s1 + v.z, s3 = s2 + v.w;
    int x = s3;
    #pragma unroll
    for (int o = 1; o < 32; o <<= 1) {
        int y = __shfl_up_sync(0xffffffffu, x, o);
        if ((t & 31) >= o) x += y;
    }
    if ((t & 31) == 31) wsum[t >> 5] = x;
    __syncthreads();
    if (t < 32) {
        int w = wsum[t], xs = w;
        #pragma unroll
        for (int o = 1; o < 32; o <<= 1) {
            int y = __shfl_up_sync(0xffffffffu, xs, o);
            if (t >= o) xs += y;
        }
        if (t == 31) g_csum[cb] = xs;
        wsum[t] = xs - w;
    }
    __syncthreads();
    int excl = wsum[t >> 5] + (x - s3);
    if (i < n) {
        int4 o4 = make_int4(excl, excl + s0, excl + s1, excl + s2);
        ((int4*)off)[i >> 2] = o4;
    }
}

// Phase 2+3 fused: each block sums preceding chunk totals itself (<=25 ints),
// adds base, and initializes cur = off (fill cursor).
__global__ void scan_addbase_kernel() {
    int cb = blockIdx.x;
    __shared__ int sbase;
    if (threadIdx.x == 0) {
        int lo = (cb < NCHC) ? 0 : NCHC;
        int a = 0;
        for (int i = lo; i < cb; i++) a += g_csum[i];
        sbase = a;
    }
    __syncthreads();
    int bval = sbase;
    int* off; int* cur; int n, chunk;
    if (cb < NCHC) { off = g_off_c; cur = g_cur_c; n = NCN; chunk = cb; }
    else           { off = g_off_m; cur = g_cur_m; n = NMN; chunk = cb - NCHC; }
    int i = chunk * 4096 + threadIdx.x * 4;
    if (i < n) {
        int4 o = ((int4*)off)[i >> 2];
        o.x += bval; o.y += bval; o.z += bval; o.w += bval;
        ((int4*)off)[i >> 2] = o;
        ((int4*)cur)[i >> 2] = o;
    }
}

// Fill both CSRs in one launch; cur doubles as slot cursor (starts at off).
__global__ void fill_all_kernel(const int* __restrict__ src_c, const int* __restrict__ dst_c,
                                const int* __restrict__ src_m, const int* __restrict__ dst_m) {
    int i = blockIdx.x * blockDim.x + threadIdx.x;
    if (i >= 2 * NE) return;
    if (i < NE) {
        int p = atomicAdd(&g_cur_c[dst_c[i]], 1);
        g_eid_c[p] = src_c[i];
    } else {
        int e = i - NE;
        int p = atomicAdd(&g_cur_m[dst_m[e]], 1);
        g_eid_m[p] = src_m[e];
    }
}

// Tiny: M = W1 @ Wf (64x2), b2 = b1 @ Wf for both relations. One block, off critical path.
__global__ void make_M_kernel(const float* __restrict__ W1c, const float* __restrict__ b1c,
                              const float* __restrict__ W1m, const float* __restrict__ b1m,
                              const float* __restrict__ Wf) {
    __shared__ float sWf[FHID * 2];
    int t = threadIdx.x;  // 256 threads
    if (t < FHID * 2) sWf[t] = Wf[t];
    __syncthreads();
    const float* W1 = (t < 128) ? W1c : W1m;
    float* Mo = (t < 128) ? g_M_c : g_M_m;
    int tt = t & 127;
    int k = tt >> 1, o = tt & 1;
    float s = 0.f;
    #pragma unroll 8
    for (int j = 0; j < FHID; j++) s += W1[k * FHID + j] * sWf[j * 2 + o];
    Mo[k * 2 + o] = s;
    if (t < 2) {
        float s2 = 0.f;
        #pragma unroll 8
        for (int j = 0; j < FHID; j++) s2 += b1c[j] * sWf[j * 2 + t];
        g_b2_c[t] = s2;
    } else if (t < 4) {
        int oo = t - 2;
        float s2 = 0.f;
        #pragma unroll 8
        for (int j = 0; j < FHID; j++) s2 += b1m[j] * sWf[j * 2 + oo];
        g_b2_m[oo] = s2;
    }
}

// Fused gather-aggregate + layer0 GEMM + projection. 64 nodes/block, 256 threads.
// W0 staged in smem; off/cnt prefetched warp-wide (kills per-node pointer-chase).
// Merchant blocks FIRST (avg degree 25 vs 5).
__global__ void __launch_bounds__(256) aggmm_kernel(
        const float* __restrict__ feat,
        const float* __restrict__ W0c, const float* __restrict__ b0c,
        const float* __restrict__ W0m, const float* __restrict__ b0m) {
    extern __shared__ float dsm[];
    float* sA = dsm;
    float4* sWlo = (float4*)(dsm + 64 * SASTR);
    float4* sWhi = sWlo + FIN * 8;

    bool isC = blockIdx.x >= NBM;
    int base = (isC ? blockIdx.x - NBM : blockIdx.x) * 64;
    int n = isC ? NCN : NMN;
    const int*   off = isC ? g_off_c : g_off_m;
    const int*   cnt = isC ? g_cnt_t2c : g_cnt_t2m;
    const int*   eid = isC ? g_eid_c : g_eid_m;
    const float* W0  = isC ? W0c : W0m;
    const float* b0  = isC ? b0c : b0m;
    const float* M   = isC ? g_M_c : g_M_m;
    const float* b2  = isC ? g_b2_c : g_b2_m;
    float*       pout = isC ? g_p_c : g_p_m;

    int t = threadIdx.x;
    int w = t >> 5, lane = t & 31;
    const float4* f4 = (const float4*)feat;

    // ---- Stage W0 into smem (contiguous 128B per k-row -> conflict-free LDS.128) ----
    {
        const float4* W4 = (const float4*)W0;
        #pragma unroll
        for (int i = t; i < FIN * 8; i += 256) {
            sWlo[i] = __ldg(W4 + 2 * i);
            sWhi[i] = __ldg(W4 + 2 * i + 1);
        }
    }

    // ---- Warp-prefetch off/cnt for this warp's 8 nodes (one predicated LDG) ----
    // lanes 0..7: off[node i], lanes 8..15: cnt[node i]
    int pre = 0;
    {
        int idx = lane & 7;
        int gnl = base + w * 8 + idx;
        if (lane < 16 && gnl < n)
            pre = (lane < 8) ? __ldg(&off[gnl]) : __ldg(&cnt[gnl]);
    }

    // ---- Phase 1: gather-aggregate into smem (MLP=8) ----
    #pragma unroll 1
    for (int i = 0; i < 8; i++) {
        int nd = w * 8 + i;
        int gn = base + nd;
        float4 acc = make_float4(0.f, 0.f, 0.f, 0.f);
        int o = __shfl_sync(0xffffffffu, pre, i);
        int c = (gn < n) ? __shfl_sync(0xffffffffu, pre, 8 + i) : 0;
        for (int b = 0; b < c; b += 32) {
            int m = min(32, c - b);
            int sreg = (lane < m) ? eid[o + b + lane] : 0;
            for (int j0 = 0; j0 < m; j0 += 8) {
                int jm = min(8, m - j0);
                float4 v[8];
                #pragma unroll
                for (int j = 0; j < 8; j++) {
                    int s = __shfl_sync(0xffffffffu, sreg, j0 + j);
                    if (j < jm) v[j] = __ldg(f4 + (size_t)s * (FIN / 4) + lane);
                }
                #pragma unroll
                for (int j = 0; j < 8; j++) {
                    if (j < jm) {
                        acc.x += v[j].x; acc.y += v[j].y; acc.z += v[j].z; acc.w += v[j].w;
                    }
                }
            }
        }
        ((float4*)(sA + nd * SASTR))[lane] = acc;
    }
    __syncthreads();   // covers sA and staged W0

    // ---- Phase 2: GEMM (W from smem) + epilogue ----
    int cg = t & 7;       // col group: cols [cg*8, cg*8+8)
    int ng = t >> 3;      // 0..31; this thread owns nodes ng and ng+32

    unsigned long long acc[2][4];
    #pragma unroll
    for (int a = 0; a < 2; a++)
        #pragma unroll
        for (int p = 0; p < 4; p++) acc[a][p] = 0ull;

    const ulonglong2* Wlo8 = (const ulonglong2*)sWlo;
    const ulonglong2* Whi8 = (const ulonglong2*)sWhi;
    #pragma unroll 2
    for (int k = 0; k < FIN; k++) {
        float a0 = sA[ng * SASTR + k];
        float a1 = sA[(ng + 32) * SASTR + k];
        unsigned long long aa0, aa1;
        asm("mov.b64 %0,{%1,%1};" : "=l"(aa0) : "f"(a0));
        asm("mov.b64 %0,{%1,%1};" : "=l"(aa1) : "f"(a1));
        ulonglong2 wlo = Wlo8[k * 8 + cg];
        ulonglong2 whi = Whi8[k * 8 + cg];
        #define FMA2(A, B, Cc) asm("fma.rn.f32x2 %0,%1,%2,%0;" : "+l"(A) : "l"(B), "l"(Cc))
        FMA2(acc[0][0], aa0, wlo.x); FMA2(acc[0][1], aa0, wlo.y);
        FMA2(acc[0][2], aa0, whi.x); FMA2(acc[0][3], aa0, whi.y);
        FMA2(acc[1][0], aa1, wlo.x); FMA2(acc[1][1], aa1, wlo.y);
        FMA2(acc[1][2], aa1, whi.x); FMA2(acc[1][3], aa1, whi.y);
        #undef FMA2
    }

    #pragma unroll
    for (int a = 0; a < 2; a++) {
        int gn = base + ng + a * 32;
        int c = (gn < n) ? cnt[gn] : 0;
        float p0 = 0.f, p1 = 0.f;
        if (c > 0) {
            float inv = 1.f / (float)c;
            #pragma unroll
            for (int p = 0; p < 4; p++) {
                float zlo, zhi;
                asm("mov.b64 {%0,%1},%2;" : "=f"(zlo), "=f"(zhi) : "l"(acc[a][p]));
                int col = cg * 8 + 2 * p;
                float h = zlo * inv + b0[col];
                h = (h > 0.f) ? h : 0.01f * h;
                p0 += h * M[col * 2];
                p1 += h * M[col * 2 + 1];
                h = zhi * inv + b0[col + 1];
                h = (h > 0.f) ? h : 0.01f * h;
                p0 += h * M[(col + 1) * 2];
                p1 += h * M[(col + 1) * 2 + 1];
            }
        }
        #pragma unroll
        for (int o = 4; o; o >>= 1) {
            p0 += __shfl_down_sync(0xffffffffu, p0, o, 8);
            p1 += __shfl_down_sync(0xffffffffu, p1, o, 8);
        }
        if (cg == 0 && gn < n) {
            pout[gn * 2]     = p0 + b2[0];
            pout[gn * 2 + 1] = p1 + b2[1];
        }
    }
}

__global__ void out_init_kernel(float* __restrict__ out, const float* __restrict__ bf) {
    int i = blockIdx.x * blockDim.x + threadIdx.x;
    if (i < NTN) ((float2*)out)[i] = make_float2(bf[0], bf[1]);
}

__global__ void scatter_all_kernel(const int* __restrict__ src_c, const int* __restrict__ dst_c,
                                   const int* __restrict__ src_m, const int* __restrict__ dst_m,
                                   float* __restrict__ out) {
    int i = blockIdx.x * blockDim.x + threadIdx.x;
    if (i >= 2 * NE) return;
    int s, d;
    const float* p;
    const int* cnt;
    if (i < NE) { s = src_c[i]; d = dst_c[i]; p = g_p_c; cnt = g_cnt_c2t; }
    else        { int e = i - NE; s = src_m[e]; d = dst_m[e]; p = g_p_m; cnt = g_cnt_m2t; }
    float inv = 1.f / (float)cnt[d];
    float a = p[2 * s] * inv;
    float b = p[2 * s + 1] * inv;
    float* ap = out + 2 * (size_t)d;
    asm volatile("red.global.add.v2.f32 [%0], {%1,%2};"
                 :: "l"(ap), "f"(a), "f"(b) : "memory");
}

// ---------------- launch ----------------
extern "C" void kernel_launch(void* const* d_in, const int* in_sizes, int n_in,
                              void* d_out, int out_size) {
    const float* feat    = (const float*)d_in[0];
    const int* src_c2t   = (const int*)d_in[3];
    const int* dst_c2t   = (const int*)d_in[4];
    const int* src_m2t   = (const int*)d_in[5];
    const int* dst_m2t   = (const int*)d_in[6];
    const int* src_t2c   = (const int*)d_in[7];
    const int* dst_t2c   = (const int*)d_in[8];
    const int* src_t2m   = (const int*)d_in[9];
    const int* dst_t2m   = (const int*)d_in[10];
    const float* W1_c2t  = (const float*)d_in[13];
    const float* b1_c2t  = (const float*)d_in[14];
    const float* W1_m2t  = (const float*)d_in[17];
    const float* b1_m2t  = (const float*)d_in[18];
    const float* W0_t2c  = (const float*)d_in[19];
    const float* b0_t2c  = (const float*)d_in[20];
    const float* W0_t2m  = (const float*)d_in[23];
    const float* b0_t2m  = (const float*)d_in[24];
    const float* Wf      = (const float*)d_in[27];
    const float* bf      = (const float*)d_in[28];
    float* out = (float*)d_out;

    const int TB = 256;

    // Allow >48KB dynamic smem for aggmm (host-side attribute; not a capture op).
    cudaFuncSetAttribute(aggmm_kernel, cudaFuncAttributeMaxDynamicSharedMemorySize, AGG_SMEM);

    // One side stream (proven-clean resource pattern).
    cudaStream_t s2;
    cudaStreamCreateWithFlags(&s2, cudaStreamNonBlocking);
    cudaEvent_t evF, evM, evB;
    cudaEventCreateWithFlags(&evF, cudaEventDisableTiming);
    cudaEventCreateWithFlags(&evM, cudaEventDisableTiming);
    cudaEventCreateWithFlags(&evB, cudaEventDisableTiming);

    cudaEventRecord(evF, 0);
    cudaStreamWaitEvent(s2, evF, 0);

    // stream B: make_M FIRST (aggmm's only B-dependency), then scatter-side prep.
    make_M_kernel<<<1, 256, 0, s2>>>(W1_c2t, b1_c2t, W1_m2t, b1_m2t, Wf);
    cudaEventRecord(evM, s2);
    initB_kernel<<<1024, TB, 0, s2>>>();
    countB_kernel<<<(2 * NE + TB - 1) / TB, TB, 0, s2>>>(dst_c2t, dst_m2t);
    out_init_kernel<<<(NTN + TB - 1) / TB, TB, 0, s2>>>(out, bf);
    cudaEventRecord(evB, s2);

    // stream A (default): CSR build -> fused agg+GEMM -> scatter
    initA_kernel<<<512, TB>>>();
    countA_kernel<<<(2 * NE + TB - 1) / TB, TB>>>(dst_t2c, dst_t2m);
    scan_local_kernel<<<NCHC + NCHM, 1024>>>();
    scan_addbase_kernel<<<NCHC + NCHM, 1024>>>();
    fill_all_kernel<<<(2 * NE + TB - 1) / TB, TB>>>(src_t2c, dst_t2c, src_t2m, dst_t2m);

    cudaStreamWaitEvent((cudaStream_t)0, evM, 0);   // make_M before aggmm
    aggmm_kernel<<<NBC + NBM, 256, AGG_SMEM>>>(feat, W0_t2c, b0_t2c, W0_t2m, b0_t2m);
    cudaStreamWaitEvent((cudaStream_t)0, evB, 0);   // counts + out_init before scatter
    scatter_all_kernel<<<(2 * NE + TB - 1) / TB, TB>>>(src_c2t, dst_c2t, src_m2t, dst_m2t, out);
}